// round 12
// baseline (speedup 1.0000x reference)
#include <cuda_runtime.h>
#include <cuda_fp16.h>
#include <stdint.h>

#define N_NODES 50000
#define D 64
#define CAP 96                  // bucket capacity (deg ~ Poisson(16); P(>=96) ~ 0)
#define TR 64                   // gemm node-tile rows

// ---------------- device scratch (no allocation allowed) ----------------
__device__ float  g_h0[N_NODES * D];
__device__ float  g_h1[N_NODES * D];
__device__ __half g_yl[N_NODES * D];
__device__ float  g_yr[N_NODES * D];
__device__ int    g_cnt[N_NODES];
__device__ int    g_bkt[N_NODES * CAP];
__device__ int    g_is64;

// ---------------- init: zero counters + dtype detection ------------------
// If edge_index is int64, all high 32-bit words are 0 (ids < 50000).
__global__ void init_kernel(const unsigned* __restrict__ w) {
    int gt = blockIdx.x * blockDim.x + threadIdx.x;
    if (gt < N_NODES) g_cnt[gt] = 0;
    if (blockIdx.x == 0) {
        __shared__ int ok;
        if (threadIdx.x == 0) ok = 1;
        __syncthreads();
        for (int i = threadIdx.x; i < 4096; i += blockDim.x)
            if (w[2 * i + 1] != 0u) ok = 0;
        __syncthreads();
        if (threadIdx.x == 0) g_is64 = ok;
    }
}

__device__ __forceinline__ int load_idx(const void* ei, long long pos, int is64) {
    if (is64) return (int)((const long long*)ei)[pos];
    return ((const int*)ei)[pos];
}

// ---------------- bucket fill: 8 edges/thread, single pass ---------------
__global__ void fill_bucket_kernel(const void* __restrict__ ei, int E) {
    int is64 = g_is64;
    long long t = (long long)blockIdx.x * blockDim.x + threadIdx.x;
    long long e = t * 8;
    if (e >= E) return;
    if (e + 8 <= E && (E & 3) == 0) {
        int s[8], d[8];
        if (is64) {
            const longlong2* sp = (const longlong2*)ei + (e >> 1);
            const longlong2* dp = (const longlong2*)((const long long*)ei + E) + (e >> 1);
#pragma unroll
            for (int q = 0; q < 4; q++) {
                longlong2 sv = sp[q];
                longlong2 dv = dp[q];
                s[2 * q] = (int)sv.x; s[2 * q + 1] = (int)sv.y;
                d[2 * q] = (int)dv.x; d[2 * q + 1] = (int)dv.y;
            }
        } else {
            const int4* sp = (const int4*)ei + (e >> 2);
            const int4* dp = (const int4*)((const int*)ei + E) + (e >> 2);
#pragma unroll
            for (int q = 0; q < 2; q++) {
                int4 sv = sp[q];
                int4 dv = dp[q];
                s[4 * q] = sv.x; s[4 * q + 1] = sv.y;
                s[4 * q + 2] = sv.z; s[4 * q + 3] = sv.w;
                d[4 * q] = dv.x; d[4 * q + 1] = dv.y;
                d[4 * q + 2] = dv.z; d[4 * q + 3] = dv.w;
            }
        }
        int p[8];
#pragma unroll
        for (int q = 0; q < 8; q++) p[q] = atomicAdd(&g_cnt[d[q]], 1);
#pragma unroll
        for (int q = 0; q < 8; q++)
            if (p[q] < CAP) g_bkt[d[q] * CAP + p[q]] = s[q];
    } else {
        for (long long q = e; q < E && q < e + 8; q++) {
            int src = load_idx(ei, q, is64);
            int dst = load_idx(ei, E + q, is64);
            int p = atomicAdd(&g_cnt[dst], 1);
            if (p < CAP) g_bkt[dst * CAP + p] = src;
        }
    }
}

// ---------------- packed fp32x2 FMA (FFMA2) -------------------------------
__device__ __forceinline__ void ffma2(unsigned long long& acc,
                                      unsigned long long a,
                                      unsigned long long b) {
    asm("fma.rn.f32x2 %0, %1, %2, %0;" : "+l"(acc) : "l"(a), "l"(b));
}
__device__ __forceinline__ unsigned long long pack2(float v) {
    unsigned long long r;
    unsigned u = __float_as_uint(v);
    asm("mov.b64 %0, {%1, %1};" : "=l"(r) : "r"(u));
    return r;
}

// ---------------- dual GEMM: Yl(fp16) = h@Wl, Yr = h@Wr + b ---------------
__global__ void __launch_bounds__(256, 4)
gemm_kernel(const float* __restrict__ in, const float* __restrict__ Wl,
            const float* __restrict__ Wr, const float* __restrict__ b,
            __half* __restrict__ Yl, float* __restrict__ Yr) {
    __shared__ float sWl[D * D];
    __shared__ float sWr[D * D];
    __shared__ float sH[TR * D];

    int tid = threadIdx.x;
    const float4* Wl4 = (const float4*)Wl;
    const float4* Wr4 = (const float4*)Wr;
#pragma unroll
    for (int i = 0; i < 4; i++) {
        ((float4*)sWl)[tid + i * 256] = Wl4[tid + i * 256];
        ((float4*)sWr)[tid + i * 256] = Wr4[tid + i * 256];
    }
    int row0 = blockIdx.x * TR;
#pragma unroll
    for (int i = 0; i < 4; i++) {
        int f4 = tid + i * 256;
        int row = row0 + (f4 >> 4);
        float4 v = make_float4(0.f, 0.f, 0.f, 0.f);
        if (row < N_NODES) v = ((const float4*)in)[(long long)row * 16 + (f4 & 15)];
        ((float4*)sH)[f4] = v;
    }
    __syncthreads();

    int rt = tid >> 4;      // rows rt*4 .. rt*4+3
    int ct = tid & 15;      // cols ct*4 .. ct*4+3

    unsigned long long al[4][2], ar[4][2];
#pragma unroll
    for (int i = 0; i < 4; i++) {
        al[i][0] = 0ull; al[i][1] = 0ull;
        ar[i][0] = 0ull; ar[i][1] = 0ull;
    }

#pragma unroll 16
    for (int k = 0; k < D; k++) {
        ulonglong2 wl2 = *(const ulonglong2*)(sWl + k * D + ct * 4);
        ulonglong2 wr2 = *(const ulonglong2*)(sWr + k * D + ct * 4);
#pragma unroll
        for (int i = 0; i < 4; i++) {
            unsigned long long h2 = pack2(sH[(rt * 4 + i) * D + k]);
            ffma2(al[i][0], h2, wl2.x);
            ffma2(al[i][1], h2, wl2.y);
            ffma2(ar[i][0], h2, wr2.x);
            ffma2(ar[i][1], h2, wr2.y);
        }
    }

    float4 bv = ((const float4*)b)[ct];
#pragma unroll
    for (int i = 0; i < 4; i++) {
        int row = row0 + rt * 4 + i;
        if (row < N_NODES) {
            float2 l0 = *(float2*)&al[i][0];
            float2 l1 = *(float2*)&al[i][1];
            __half2 hl0 = __floats2half2_rn(l0.x, l0.y);
            __half2 hl1 = __floats2half2_rn(l1.x, l1.y);
            uint2 hv;
            hv.x = *(unsigned*)&hl0;
            hv.y = *(unsigned*)&hl1;
            *(uint2*)(Yl + (long long)row * D + ct * 4) = hv;

            float2 r0 = *(float2*)&ar[i][0];
            float2 r1 = *(float2*)&ar[i][1];
            float4 rv = make_float4(r0.x + bv.x, r0.y + bv.y,
                                    r1.x + bv.z, r1.y + bv.w);
            ((float4*)Yr)[(long long)row * 16 + ct] = rv;
        }
    }
}

// ---------------- aggregate: out = relu?(Yr + mean_nbr(Yl)) ---------------
// One warp per node. 8 lanes per neighbor, LDG.128 per lane (16B = 8 halfs).
// Per <=32-neighbor chunk, accumulate in half2 (HADD2, <=8 fp16 adds per
// accumulator), convert to fp32 once per chunk. Butterfly reduce at end.
__global__ void __launch_bounds__(256)
aggregate_kernel(const __half* __restrict__ Yl, const float* __restrict__ Yr,
                 float* __restrict__ out, int relu) {
    int gt = blockIdx.x * blockDim.x + threadIdx.x;
    int n = gt >> 5;
    if (n >= N_NODES) return;
    int lane = gt & 31;
    int g = lane >> 3;        // neighbor sub-slot (0..3)
    int sub = lane & 7;       // owns halfs [sub*8 .. sub*8+7]
    const unsigned FULL = 0xffffffffu;

    int deg = g_cnt[n];
    int m_all = deg < CAP ? deg : CAP;
    const int* bkt = g_bkt + n * CAP;

    float a0 = 0.f, a1 = 0.f, a2 = 0.f, a3 = 0.f;
    float a4 = 0.f, a5 = 0.f, a6 = 0.f, a7 = 0.f;

    for (int base = 0; base < m_all; base += 32) {
        int m = m_all - base;
        if (m > 32) m = 32;
        int myidx = (lane < m) ? bkt[base + lane] : 0;
        __half2 h0 = __float2half2_rn(0.f);
        __half2 h1 = h0, h2 = h0, h3 = h0;
        for (int j = 0; j < m; j += 8) {
            int j0 = j + g, j1 = j + 4 + g;
            int id0 = __shfl_sync(FULL, myidx, j0 & 31);
            int id1 = __shfl_sync(FULL, myidx, j1 & 31);
            uint4 v0 = make_uint4(0u, 0u, 0u, 0u);
            uint4 v1 = make_uint4(0u, 0u, 0u, 0u);
            if (j0 < m) v0 = *(const uint4*)(Yl + (long long)id0 * D + sub * 8);
            if (j1 < m) v1 = *(const uint4*)(Yl + (long long)id1 * D + sub * 8);
            h0 = __hadd2(h0, __hadd2(*(__half2*)&v0.x, *(__half2*)&v1.x));
            h1 = __hadd2(h1, __hadd2(*(__half2*)&v0.y, *(__half2*)&v1.y));
            h2 = __hadd2(h2, __hadd2(*(__half2*)&v0.z, *(__half2*)&v1.z));
            h3 = __hadd2(h3, __hadd2(*(__half2*)&v0.w, *(__half2*)&v1.w));
        }
        float2 f;
        f = __half22float2(h0); a0 += f.x; a1 += f.y;
        f = __half22float2(h1); a2 += f.x; a3 += f.y;
        f = __half22float2(h2); a4 += f.x; a5 += f.y;
        f = __half22float2(h3); a6 += f.x; a7 += f.y;
    }

    // butterfly reduce across the 4 neighbor sub-slots (lane bits 3,4)
#define RED(v) v += __shfl_xor_sync(FULL, v, 8); v += __shfl_xor_sync(FULL, v, 16);
    RED(a0) RED(a1) RED(a2) RED(a3) RED(a4) RED(a5) RED(a6) RED(a7)
#undef RED

    float s0, s1;
    if (g == 0)      { s0 = a0; s1 = a1; }
    else if (g == 1) { s0 = a2; s1 = a3; }
    else if (g == 2) { s0 = a4; s1 = a5; }
    else             { s0 = a6; s1 = a7; }

    float inv = 1.0f / (float)(deg > 0 ? deg : 1);
    int col = sub * 8 + g * 2;
    float2 r = *(const float2*)(Yr + (long long)n * D + col);
    float o0 = r.x + s0 * inv;
    float o1 = r.y + s1 * inv;
    if (relu) { o0 = fmaxf(o0, 0.f); o1 = fmaxf(o1, 0.f); }
    float2 o; o.x = o0; o.y = o1;
    *(float2*)(out + (long long)n * D + col) = o;
}

// ---------------- launch --------------------------------------------------
extern "C" void kernel_launch(void* const* d_in, const int* in_sizes, int n_in,
                              void* d_out, int out_size) {
    const float* x   = (const float*)d_in[0];
    const void*  ei  = d_in[1];
    const float* Wl1 = (const float*)d_in[2];
    const float* Wr1 = (const float*)d_in[3];
    const float* b1  = (const float*)d_in[4];
    const float* Wl2 = (const float*)d_in[5];
    const float* Wr2 = (const float*)d_in[6];
    const float* b2  = (const float*)d_in[7];
    const float* Wl3 = (const float*)d_in[8];
    const float* Wr3 = (const float*)d_in[9];
    const float* b3  = (const float*)d_in[10];
    float* out = (float*)d_out;

    int E = in_sizes[1] / 2;

    float *h0, *h1, *yr;
    __half* yl;
    { void* p; cudaGetSymbolAddress(&p, g_h0); h0 = (float*)p; }
    { void* p; cudaGetSymbolAddress(&p, g_h1); h1 = (float*)p; }
    { void* p; cudaGetSymbolAddress(&p, g_yl); yl = (__half*)p; }
    { void* p; cudaGetSymbolAddress(&p, g_yr); yr = (float*)p; }

    const int init_blocks = (N_NODES + 255) / 256;           // 196
    const int fill_blocks = (E + 256 * 8 - 1) / (256 * 8);   // 8 edges/thread
    const int gemm_blocks = (N_NODES + TR - 1) / TR;         // 782
    const int agg_blocks  = (N_NODES * 32 + 255) / 256;      // 6250

    // bucket build (once; shared by all 3 layers)
    init_kernel<<<init_blocks, 256>>>((const unsigned*)ei);
    fill_bucket_kernel<<<fill_blocks, 256>>>(ei, E);

    // layer 1
    gemm_kernel<<<gemm_blocks, 256>>>(x, Wl1, Wr1, b1, yl, yr);
    aggregate_kernel<<<agg_blocks, 256>>>(yl, yr, h0, 1);
    // layer 2
    gemm_kernel<<<gemm_blocks, 256>>>(h0, Wl2, Wr2, b2, yl, yr);
    aggregate_kernel<<<agg_blocks, 256>>>(yl, yr, h1, 1);
    // layer 3
    gemm_kernel<<<gemm_blocks, 256>>>(h1, Wl3, Wr3, b3, yl, yr);
    aggregate_kernel<<<agg_blocks, 256>>>(yl, yr, out, 0);
}

// round 14
// speedup vs baseline: 1.0788x; 1.0788x over previous
#include <cuda_runtime.h>
#include <cuda_fp16.h>
#include <stdint.h>

#define N_NODES 50000
#define D 64
#define CAP 96                  // bucket capacity (deg ~ Poisson(16); P(>=96) ~ 0)
#define TR 64                   // gemm node-tile rows

// ---------------- device scratch (no allocation allowed) ----------------
__device__ float  g_h0[N_NODES * D];
__device__ float  g_h1[N_NODES * D];
__device__ __half g_yl[N_NODES * D];
__device__ float  g_yr[N_NODES * D];
__device__ int    g_cnt[N_NODES];
__device__ int    g_bkt[N_NODES * CAP];
__device__ int    g_is64;

// ---------------- init: zero counters + dtype detection ------------------
__global__ void init_kernel(const unsigned* __restrict__ w) {
    int gt = blockIdx.x * blockDim.x + threadIdx.x;
    if (gt < N_NODES) g_cnt[gt] = 0;
    if (blockIdx.x == 0) {
        __shared__ int ok;
        if (threadIdx.x == 0) ok = 1;
        __syncthreads();
        for (int i = threadIdx.x; i < 4096; i += blockDim.x)
            if (w[2 * i + 1] != 0u) ok = 0;
        __syncthreads();
        if (threadIdx.x == 0) g_is64 = ok;
    }
}

__device__ __forceinline__ int load_idx(const void* ei, long long pos, int is64) {
    if (is64) return (int)((const long long*)ei)[pos];
    return ((const int*)ei)[pos];
}

// ---------------- bucket fill: 8 edges/thread, single pass ---------------
__global__ void fill_bucket_kernel(const void* __restrict__ ei, int E) {
    int is64 = g_is64;
    long long t = (long long)blockIdx.x * blockDim.x + threadIdx.x;
    long long e = t * 8;
    if (e >= E) return;
    if (e + 8 <= E && (E & 3) == 0) {
        int s[8], d[8];
        if (is64) {
            const longlong2* sp = (const longlong2*)ei + (e >> 1);
            const longlong2* dp = (const longlong2*)((const long long*)ei + E) + (e >> 1);
#pragma unroll
            for (int q = 0; q < 4; q++) {
                longlong2 sv = sp[q];
                longlong2 dv = dp[q];
                s[2 * q] = (int)sv.x; s[2 * q + 1] = (int)sv.y;
                d[2 * q] = (int)dv.x; d[2 * q + 1] = (int)dv.y;
            }
        } else {
            const int4* sp = (const int4*)ei + (e >> 2);
            const int4* dp = (const int4*)((const int*)ei + E) + (e >> 2);
#pragma unroll
            for (int q = 0; q < 2; q++) {
                int4 sv = sp[q];
                int4 dv = dp[q];
                s[4 * q] = sv.x; s[4 * q + 1] = sv.y;
                s[4 * q + 2] = sv.z; s[4 * q + 3] = sv.w;
                d[4 * q] = dv.x; d[4 * q + 1] = dv.y;
                d[4 * q + 2] = dv.z; d[4 * q + 3] = dv.w;
            }
        }
        int p[8];
#pragma unroll
        for (int q = 0; q < 8; q++) p[q] = atomicAdd(&g_cnt[d[q]], 1);
#pragma unroll
        for (int q = 0; q < 8; q++)
            if (p[q] < CAP) g_bkt[d[q] * CAP + p[q]] = s[q];
    } else {
        for (long long q = e; q < E && q < e + 8; q++) {
            int src = load_idx(ei, q, is64);
            int dst = load_idx(ei, E + q, is64);
            int p = atomicAdd(&g_cnt[dst], 1);
            if (p < CAP) g_bkt[dst * CAP + p] = src;
        }
    }
}

// ---------------- packed fp32x2 FMA (FFMA2) -------------------------------
__device__ __forceinline__ void ffma2(unsigned long long& acc,
                                      unsigned long long a,
                                      unsigned long long b) {
    asm("fma.rn.f32x2 %0, %1, %2, %0;" : "+l"(acc) : "l"(a), "l"(b));
}
__device__ __forceinline__ unsigned long long pack2(float v) {
    unsigned long long r;
    unsigned u = __float_as_uint(v);
    asm("mov.b64 %0, {%1, %1};" : "=l"(r) : "r"(u));
    return r;
}

// ---------------- dual GEMM: Yl(fp16) = h@Wl, Yr = h@Wr + b ---------------
__global__ void __launch_bounds__(256, 4)
gemm_kernel(const float* __restrict__ in, const float* __restrict__ Wl,
            const float* __restrict__ Wr, const float* __restrict__ b,
            __half* __restrict__ Yl, float* __restrict__ Yr) {
    __shared__ float sWl[D * D];
    __shared__ float sWr[D * D];
    __shared__ float sH[TR * D];

    int tid = threadIdx.x;
    const float4* Wl4 = (const float4*)Wl;
    const float4* Wr4 = (const float4*)Wr;
#pragma unroll
    for (int i = 0; i < 4; i++) {
        ((float4*)sWl)[tid + i * 256] = Wl4[tid + i * 256];
        ((float4*)sWr)[tid + i * 256] = Wr4[tid + i * 256];
    }
    int row0 = blockIdx.x * TR;
#pragma unroll
    for (int i = 0; i < 4; i++) {
        int f4 = tid + i * 256;
        int row = row0 + (f4 >> 4);
        float4 v = make_float4(0.f, 0.f, 0.f, 0.f);
        if (row < N_NODES) v = ((const float4*)in)[(long long)row * 16 + (f4 & 15)];
        ((float4*)sH)[f4] = v;
    }
    __syncthreads();

    int rt = tid >> 4;      // rows rt*4 .. rt*4+3
    int ct = tid & 15;      // cols ct*4 .. ct*4+3

    unsigned long long al[4][2], ar[4][2];
#pragma unroll
    for (int i = 0; i < 4; i++) {
        al[i][0] = 0ull; al[i][1] = 0ull;
        ar[i][0] = 0ull; ar[i][1] = 0ull;
    }

#pragma unroll 16
    for (int k = 0; k < D; k++) {
        ulonglong2 wl2 = *(const ulonglong2*)(sWl + k * D + ct * 4);
        ulonglong2 wr2 = *(const ulonglong2*)(sWr + k * D + ct * 4);
#pragma unroll
        for (int i = 0; i < 4; i++) {
            unsigned long long h2 = pack2(sH[(rt * 4 + i) * D + k]);
            ffma2(al[i][0], h2, wl2.x);
            ffma2(al[i][1], h2, wl2.y);
            ffma2(ar[i][0], h2, wr2.x);
            ffma2(ar[i][1], h2, wr2.y);
        }
    }

    float4 bv = ((const float4*)b)[ct];
#pragma unroll
    for (int i = 0; i < 4; i++) {
        int row = row0 + rt * 4 + i;
        if (row < N_NODES) {
            float2 l0 = *(float2*)&al[i][0];
            float2 l1 = *(float2*)&al[i][1];
            __half2 hl0 = __floats2half2_rn(l0.x, l0.y);
            __half2 hl1 = __floats2half2_rn(l1.x, l1.y);
            uint2 hv;
            hv.x = *(unsigned*)&hl0;
            hv.y = *(unsigned*)&hl1;
            *(uint2*)(Yl + (long long)row * D + ct * 4) = hv;

            float2 r0 = *(float2*)&ar[i][0];
            float2 r1 = *(float2*)&ar[i][1];
            float4 rv = make_float4(r0.x + bv.x, r0.y + bv.y,
                                    r1.x + bv.z, r1.y + bv.w);
            ((float4*)Yr)[(long long)row * 16 + ct] = rv;
        }
    }
}

// ---------------- aggregate: out = relu?(Yr + mean_nbr(Yl)) ---------------
// 4 nodes per warp; 8 lanes per node. Lane owns cols [sub*8, sub*8+8) of its
// node -> NO cross-lane reduction. 8 gather loads batched before accumulation
// -> high MLP. fp32 accumulation.
__global__ void __launch_bounds__(256)
aggregate_kernel(const __half* __restrict__ Yl, const float* __restrict__ Yr,
                 float* __restrict__ out, int relu) {
    int gt = blockIdx.x * blockDim.x + threadIdx.x;
    int w = gt >> 5;
    int lane = gt & 31;
    int g = lane >> 3;        // node sub-group (0..3)
    int sub = lane & 7;       // owns halfs [sub*8 .. sub*8+7]
    int n = w * 4 + g;
    const unsigned FULL = 0xffffffffu;

    bool valid = (n < N_NODES);
    int deg = valid ? g_cnt[n] : 0;
    int m = deg < CAP ? deg : CAP;
    int mmax = __reduce_max_sync(FULL, m);
    const int* bp = g_bkt + (long long)n * CAP;

    float a0 = 0.f, a1 = 0.f, a2 = 0.f, a3 = 0.f;
    float a4 = 0.f, a5 = 0.f, a6 = 0.f, a7 = 0.f;

    for (int base = 0; base < mmax; base += 8) {
        int idx = 0;
        if (base + sub < m) idx = bp[base + sub];
        uint4 v[8];
#pragma unroll
        for (int jj = 0; jj < 8; jj++) {
            int id = __shfl_sync(FULL, idx, (g << 3) + jj);
            v[jj] = make_uint4(0u, 0u, 0u, 0u);
            if (base + jj < m)
                v[jj] = *(const uint4*)(Yl + (long long)id * D + sub * 8);
        }
#pragma unroll
        for (int jj = 0; jj < 8; jj++) {
            float2 f;
            f = __half22float2(*(__half2*)&v[jj].x); a0 += f.x; a1 += f.y;
            f = __half22float2(*(__half2*)&v[jj].y); a2 += f.x; a3 += f.y;
            f = __half22float2(*(__half2*)&v[jj].z); a4 += f.x; a5 += f.y;
            f = __half22float2(*(__half2*)&v[jj].w); a6 += f.x; a7 += f.y;
        }
    }

    if (!valid) return;
    float inv = 1.0f / (float)(deg > 0 ? deg : 1);
    long long rb = (long long)n * 16 + sub * 2;   // float4 units
    float4 r0 = ((const float4*)Yr)[rb];
    float4 r1 = ((const float4*)Yr)[rb + 1];
    float4 o0, o1;
    o0.x = r0.x + a0 * inv; o0.y = r0.y + a1 * inv;
    o0.z = r0.z + a2 * inv; o0.w = r0.w + a3 * inv;
    o1.x = r1.x + a4 * inv; o1.y = r1.y + a5 * inv;
    o1.z = r1.z + a6 * inv; o1.w = r1.w + a7 * inv;
    if (relu) {
        o0.x = fmaxf(o0.x, 0.f); o0.y = fmaxf(o0.y, 0.f);
        o0.z = fmaxf(o0.z, 0.f); o0.w = fmaxf(o0.w, 0.f);
        o1.x = fmaxf(o1.x, 0.f); o1.y = fmaxf(o1.y, 0.f);
        o1.z = fmaxf(o1.z, 0.f); o1.w = fmaxf(o1.w, 0.f);
    }
    ((float4*)out)[rb] = o0;
    ((float4*)out)[rb + 1] = o1;
}

// ---------------- launch --------------------------------------------------
extern "C" void kernel_launch(void* const* d_in, const int* in_sizes, int n_in,
                              void* d_out, int out_size) {
    const float* x   = (const float*)d_in[0];
    const void*  ei  = d_in[1];
    const float* Wl1 = (const float*)d_in[2];
    const float* Wr1 = (const float*)d_in[3];
    const float* b1  = (const float*)d_in[4];
    const float* Wl2 = (const float*)d_in[5];
    const float* Wr2 = (const float*)d_in[6];
    const float* b2  = (const float*)d_in[7];
    const float* Wl3 = (const float*)d_in[8];
    const float* Wr3 = (const float*)d_in[9];
    const float* b3  = (const float*)d_in[10];
    float* out = (float*)d_out;

    int E = in_sizes[1] / 2;

    float *h0, *h1, *yr;
    __half* yl;
    { void* p; cudaGetSymbolAddress(&p, g_h0); h0 = (float*)p; }
    { void* p; cudaGetSymbolAddress(&p, g_h1); h1 = (float*)p; }
    { void* p; cudaGetSymbolAddress(&p, g_yl); yl = (__half*)p; }
    { void* p; cudaGetSymbolAddress(&p, g_yr); yr = (float*)p; }

    const int init_blocks = (N_NODES + 255) / 256;           // 196
    const int fill_blocks = (E + 256 * 8 - 1) / (256 * 8);   // 8 edges/thread
    const int gemm_blocks = (N_NODES + TR - 1) / TR;         // 782
    const int agg_blocks  = (N_NODES + 31) / 32;             // 4 nodes/warp, 8 warps/block

    // bucket build (once; shared by all 3 layers)
    init_kernel<<<init_blocks, 256>>>((const unsigned*)ei);
    fill_bucket_kernel<<<fill_blocks, 256>>>(ei, E);

    // layer 1
    gemm_kernel<<<gemm_blocks, 256>>>(x, Wl1, Wr1, b1, yl, yr);
    aggregate_kernel<<<agg_blocks, 256>>>(yl, yr, h0, 1);
    // layer 2
    gemm_kernel<<<gemm_blocks, 256>>>(h0, Wl2, Wr2, b2, yl, yr);
    aggregate_kernel<<<agg_blocks, 256>>>(yl, yr, h1, 1);
    // layer 3
    gemm_kernel<<<gemm_blocks, 256>>>(h1, Wl3, Wr3, b3, yl, yr);
    aggregate_kernel<<<agg_blocks, 256>>>(yl, yr, out, 0);
}